// round 1
// baseline (speedup 1.0000x reference)
#include <cuda_runtime.h>
#include <cstdint>

#define Nn 100000
#define Ee 600000

// ---------------- scratch (allocation-free: __device__ globals) --------------
__device__ float g_agg[Nn * 128];
__device__ float g_t[Nn * 128];
__device__ float g_h[Nn * 128];

// ---------------- f32x2 helpers ----------------------------------------------
__device__ __forceinline__ unsigned long long pack_dup(float v) {
    unsigned long long r;
    asm("mov.b64 %0, {%1, %1};" : "=l"(r) : "f"(v));
    return r;
}
__device__ __forceinline__ void fma2(unsigned long long& acc,
                                     unsigned long long a,
                                     unsigned long long b) {
    asm("fma.rn.f32x2 %0, %1, %2, %0;" : "+l"(acc) : "l"(a), "l"(b));
}
__device__ __forceinline__ float2 unpk(unsigned long long v) {
    float2 f;
    asm("mov.b64 {%0, %1}, %2;" : "=f"(f.x), "=f"(f.y) : "l"(v));
    return f;
}
__device__ __forceinline__ void red_add_v4(float* p, float4 v) {
    asm volatile("red.global.add.v4.f32 [%0], {%1, %2, %3, %4};"
                 :: "l"(p), "f"(v.x), "f"(v.y), "f"(v.z), "f"(v.w)
                 : "memory");
}

// ---------------- init copy ---------------------------------------------------
__global__ void __launch_bounds__(256) copy_kernel(float4* __restrict__ dst,
                                                   const float4* __restrict__ src,
                                                   int n4) {
    int i = blockIdx.x * blockDim.x + threadIdx.x;
    if (i < n4) dst[i] = src[i];
}

// ---------------- fused edge kernel ------------------------------------------
// Per block: 64 edges. msg = relu(x[src] + ef @ We + be); red.add.v4 into agg[dst].
// Thread = 2 edges x 16 cols (4 strided float4 groups). f32x2 packing over col pairs.
__global__ void __launch_bounds__(256, 2)
edge_kernel(const float* __restrict__ xin,
            const int* __restrict__ src, const int* __restrict__ dst,
            const float* __restrict__ ef,
            const float* __restrict__ We, const float* __restrict__ be,
            float* __restrict__ agg) {
    __shared__ float we_s[32 * 128];                 // 16 KB, natural pairs
    __shared__ unsigned long long ef_s[64 * 33];     // dup-packed, padded rows
    __shared__ float be_s[128];
    __shared__ int s_src[64], s_dst[64];

    const int tid = threadIdx.x;
    const long base = (long)blockIdx.x * 64;

    // Load We (32x128) — 1024 float4
#pragma unroll
    for (int i = 0; i < 4; i++) {
        int f4 = tid + i * 256;
        ((float4*)we_s)[f4] = ((const float4*)We)[f4];
    }
    if (tid < 128) be_s[tid] = be[tid];
    if (tid < 64)       s_src[tid]      = src[base + tid];
    else if (tid < 128) s_dst[tid - 64] = dst[base + tid - 64];

    // Load edge_feats tile (64 x 32) and duplicate-pack
#pragma unroll
    for (int i = 0; i < 2; i++) {
        int f4 = tid + i * 256;                       // 512 float4 total
        float4 v = ((const float4*)ef)[base * 8 + f4];
        int e = f4 >> 3;
        int k4 = (f4 & 7) * 4;
        ef_s[e * 33 + k4 + 0] = pack_dup(v.x);
        ef_s[e * 33 + k4 + 1] = pack_dup(v.y);
        ef_s[e * 33 + k4 + 2] = pack_dup(v.z);
        ef_s[e * 33 + k4 + 3] = pack_dup(v.w);
    }
    __syncthreads();

    const int eg = tid >> 3;        // 0..31 -> 2 edges each
    const int cg = tid & 7;         // 0..7  -> 16 strided cols
    const int e0 = eg * 2;

    unsigned long long acc[2][8];
#pragma unroll
    for (int i = 0; i < 2; i++)
#pragma unroll
        for (int j = 0; j < 8; j++) acc[i][j] = 0ULL;

#pragma unroll
    for (int k = 0; k < 32; k++) {
        unsigned long long ea = ef_s[e0 * 33 + k];
        unsigned long long eb = ef_s[(e0 + 1) * 33 + k];
#pragma unroll
        for (int g = 0; g < 4; g++) {
            ulonglong2 w = *(const ulonglong2*)(we_s + k * 128 + 4 * (cg + 8 * g));
            fma2(acc[0][2 * g],     ea, w.x);
            fma2(acc[0][2 * g + 1], ea, w.y);
            fma2(acc[1][2 * g],     eb, w.x);
            fma2(acc[1][2 * g + 1], eb, w.y);
        }
    }

    // Epilogue: gather x[src], relu, vector reduction into agg[dst]
#pragma unroll
    for (int i = 0; i < 2; i++) {
        int e = e0 + i;
        size_t srow = (size_t)s_src[e] * 128;
        size_t drow = (size_t)s_dst[e] * 128;
#pragma unroll
        for (int g = 0; g < 4; g++) {
            int cb = 4 * (cg + 8 * g);
            float4 xv = *(const float4*)(xin + srow + cb);
            float2 fa = unpk(acc[i][2 * g]);
            float2 fb = unpk(acc[i][2 * g + 1]);
            float4 m;
            m.x = fmaxf(xv.x + fa.x + be_s[cb + 0], 0.f);
            m.y = fmaxf(xv.y + fa.y + be_s[cb + 1], 0.f);
            m.z = fmaxf(xv.z + fb.x + be_s[cb + 2], 0.f);
            m.w = fmaxf(xv.w + fb.y + be_s[cb + 3], 0.f);
            red_add_v4(agg + drow + cb, m);
        }
    }
}

// ---------------- node GEMM: out = act(A @ W + b) -----------------------------
// Cin = 128 fixed. Thread = 8 nodes (4 f32x2 node-pairs) x 8 strided cols.
// A transposed in smem (natural node pairs); W duplicate-packed in smem.
template <int COUT, int ACT>
__global__ void __launch_bounds__(256, 2)
gemm_kernel(const float* __restrict__ A, const float* __restrict__ W,
            const float* __restrict__ bias,
            float* __restrict__ out, float* __restrict__ out2, int nrows) {
    constexpr int CG = COUT / 8;     // col-groups (16 or 8)
    constexpr int NG = 256 / CG;     // node-groups (16 or 32)
    constexpr int BN = NG * 8;       // nodes per block (128 or 256)

    __shared__ float a_s[16 * BN];                   // transposed [k][node]
    __shared__ unsigned long long w_s[16 * COUT];    // dup-packed [k][col]
    __shared__ float b_s[COUT];

    const int tid = threadIdx.x;
    const int nbase = blockIdx.x * BN;
    if (tid < COUT) b_s[tid] = bias[tid];

    const int ng = tid / CG, cg = tid % CG;
    const int n0 = ng * 8;

    unsigned long long acc[4][8];
#pragma unroll
    for (int p = 0; p < 4; p++)
#pragma unroll
        for (int j = 0; j < 8; j++) acc[p][j] = 0ULL;

    for (int kt = 0; kt < 8; kt++) {
        const int k0 = kt * 16;
        __syncthreads();
        // Load A tile, transposed into smem
#pragma unroll
        for (int i = 0; i < BN / 64; i++) {
            int f4 = tid + i * 256;
            int row = f4 >> 2;
            int kq = f4 & 3;
            float4 v = make_float4(0.f, 0.f, 0.f, 0.f);
            int gr = nbase + row;
            if (gr < nrows) v = *(const float4*)(A + (size_t)gr * 128 + k0 + kq * 4);
            a_s[(kq * 4 + 0) * BN + row] = v.x;
            a_s[(kq * 4 + 1) * BN + row] = v.y;
            a_s[(kq * 4 + 2) * BN + row] = v.z;
            a_s[(kq * 4 + 3) * BN + row] = v.w;
        }
        // Load W tile, duplicate-packed
#pragma unroll
        for (int i = 0; i < COUT / 64; i++) {
            int f4 = tid + i * 256;
            int k = f4 / (COUT / 4);
            int cq = f4 % (COUT / 4);
            float4 v = *(const float4*)(W + (size_t)(k0 + k) * COUT + cq * 4);
            w_s[k * COUT + cq * 4 + 0] = pack_dup(v.x);
            w_s[k * COUT + cq * 4 + 1] = pack_dup(v.y);
            w_s[k * COUT + cq * 4 + 2] = pack_dup(v.z);
            w_s[k * COUT + cq * 4 + 3] = pack_dup(v.w);
        }
        __syncthreads();

#pragma unroll
        for (int k = 0; k < 16; k++) {
            const unsigned long long* ap =
                (const unsigned long long*)(a_s + k * BN + n0);
            ulonglong2 a01 = *(const ulonglong2*)(ap);
            ulonglong2 a23 = *(const ulonglong2*)(ap + 2);
            unsigned long long av[4] = {a01.x, a01.y, a23.x, a23.y};
            unsigned long long wv[8];
#pragma unroll
            for (int j = 0; j < 8; j++) wv[j] = w_s[k * COUT + cg + j * CG];
#pragma unroll
            for (int p = 0; p < 4; p++)
#pragma unroll
                for (int j = 0; j < 8; j++) fma2(acc[p][j], av[p], wv[j]);
        }
    }

    // Epilogue
#pragma unroll
    for (int p = 0; p < 4; p++) {
        int r0 = nbase + n0 + 2 * p;
        bool ok0 = (r0 < nrows), ok1 = (r0 + 1 < nrows);
#pragma unroll
        for (int j = 0; j < 8; j++) {
            int col = cg + j * CG;
            float2 f = unpk(acc[p][j]);
            float v0 = f.x + b_s[col];
            float v1 = f.y + b_s[col];
            if (ACT == 1) { v0 = fmaxf(v0, 0.f); v1 = fmaxf(v1, 0.f); }
            if (ACT == 2) { v0 = tanhf(v0);      v1 = tanhf(v1); }
            if (ok0) {
                out[(size_t)r0 * COUT + col] = v0;
                if (out2) out2[(size_t)r0 * COUT + col] = v0;
            }
            if (ok1) {
                out[(size_t)(r0 + 1) * COUT + col] = v1;
                if (out2) out2[(size_t)(r0 + 1) * COUT + col] = v1;
            }
        }
    }
}

// ---------------- launch ------------------------------------------------------
extern "C" void kernel_launch(void* const* d_in, const int* in_sizes, int n_in,
                              void* d_out, int out_size) {
    const float* x    = (const float*)d_in[0];
    const int*   ei   = (const int*)d_in[1];
    const float* ef   = (const float*)d_in[2];
    const float* We1  = (const float*)d_in[3];
    const float* be1  = (const float*)d_in[4];
    const float* W1a  = (const float*)d_in[5];
    const float* b1a  = (const float*)d_in[6];
    const float* W1b  = (const float*)d_in[7];
    const float* b1b  = (const float*)d_in[8];
    const float* We2  = (const float*)d_in[9];
    const float* be2  = (const float*)d_in[10];
    const float* W2a  = (const float*)d_in[11];
    const float* b2a  = (const float*)d_in[12];
    const float* W2b  = (const float*)d_in[13];
    const float* b2b  = (const float*)d_in[14];
    const float* Wfc1 = (const float*)d_in[15];
    const float* bfc1 = (const float*)d_in[16];
    const float* Wfc2 = (const float*)d_in[17];
    const float* bfc2 = (const float*)d_in[18];
    float* out = (float*)d_out;

    float *agg, *t, *h;
    cudaGetSymbolAddress((void**)&agg, g_agg);
    cudaGetSymbolAddress((void**)&t,   g_t);
    cudaGetSymbolAddress((void**)&h,   g_h);

    const int* srcp = ei;
    const int* dstp = ei + Ee;

    const int n4 = Nn * 128 / 4;                 // 3,200,000
    const int cpG = (n4 + 255) / 256;            // 12500
    const int egG = Ee / 64;                     // 9375
    const int g128 = (Nn + 127) / 128;           // 782
    const int g64  = (Nn + 255) / 256;           // 391

    // Layer 1: agg = x + sum relu(x[src] + ef@We1 + be1)
    copy_kernel<<<cpG, 256>>>((float4*)agg, (const float4*)x, n4);
    edge_kernel<<<egG, 256>>>(x, srcp, dstp, ef, We1, be1, agg);
    gemm_kernel<128, 1><<<g128, 256>>>(agg, W1a, b1a, t, nullptr, Nn);
    gemm_kernel<128, 2><<<g128, 256>>>(t, W1b, b1b, h, agg, Nn);  // h=tanh(.), agg=h

    // Layer 2
    edge_kernel<<<egG, 256>>>(h, srcp, dstp, ef, We2, be2, agg);
    gemm_kernel<128, 1><<<g128, 256>>>(agg, W2a, b2a, t, nullptr, Nn);
    gemm_kernel<128, 2><<<g128, 256>>>(t, W2b, b2b, h, nullptr, Nn);

    // Head
    gemm_kernel<128, 2><<<g128, 256>>>(h, Wfc1, bfc1, t, nullptr, Nn);
    gemm_kernel<64, 0><<<g64, 256>>>(t, Wfc2, bfc2, out, nullptr, Nn);
}

// round 2
// speedup vs baseline: 1.1130x; 1.1130x over previous
#include <cuda_runtime.h>
#include <cstdint>

#define Nn 100000
#define Ee 600000

// ---------------- scratch (allocation-free: __device__ globals) --------------
__device__ float g_agg[Nn * 128];
__device__ float g_t[Nn * 128];
__device__ float g_h[Nn * 128];

// ---------------- f32x2 / async helpers --------------------------------------
__device__ __forceinline__ unsigned long long pack_dup(float v) {
    unsigned long long r;
    asm("mov.b64 %0, {%1, %1};" : "=l"(r) : "f"(v));
    return r;
}
__device__ __forceinline__ void fma2(unsigned long long& acc,
                                     unsigned long long a,
                                     unsigned long long b) {
    asm("fma.rn.f32x2 %0, %1, %2, %0;" : "+l"(acc) : "l"(a), "l"(b));
}
__device__ __forceinline__ float2 unpk(unsigned long long v) {
    float2 f;
    asm("mov.b64 {%0, %1}, %2;" : "=f"(f.x), "=f"(f.y) : "l"(v));
    return f;
}
__device__ __forceinline__ void red_add_v4(float* p, float4 v) {
    asm volatile("red.global.add.v4.f32 [%0], {%1, %2, %3, %4};"
                 :: "l"(p), "f"(v.x), "f"(v.y), "f"(v.z), "f"(v.w)
                 : "memory");
}
__device__ __forceinline__ uint32_t smem_u32(const void* p) {
    return (uint32_t)__cvta_generic_to_shared(p);
}
__device__ __forceinline__ void cp_async16(uint32_t dst, const void* src) {
    asm volatile("cp.async.cg.shared.global [%0], [%1], 16;"
                 :: "r"(dst), "l"(src));
}
__device__ __forceinline__ void cp_commit() {
    asm volatile("cp.async.commit_group;");
}
__device__ __forceinline__ void cp_wait1() {
    asm volatile("cp.async.wait_group 1;" ::: "memory");
}
__device__ __forceinline__ void cp_wait0() {
    asm volatile("cp.async.wait_group 0;" ::: "memory");
}

// ---------------- init copy ---------------------------------------------------
__global__ void __launch_bounds__(256) copy_kernel(float4* __restrict__ dst,
                                                   const float4* __restrict__ src,
                                                   int n4) {
    int i = blockIdx.x * blockDim.x + threadIdx.x;
    if (i < n4) dst[i] = src[i];
}

// ---------------- fused edge kernel ------------------------------------------
// Per block: 64 edges. msg = relu(x[src] + ef @ We + be); red.add.v4 into agg[dst].
__global__ void __launch_bounds__(256, 3)
edge_kernel(const float* __restrict__ xin,
            const int* __restrict__ src, const int* __restrict__ dst,
            const float* __restrict__ ef,
            const float* __restrict__ We, const float* __restrict__ be,
            float* __restrict__ agg) {
    __shared__ float we_s[32 * 128];                 // 16 KB, natural pairs
    __shared__ unsigned long long ef_s[64 * 33];     // dup-packed, padded rows
    __shared__ float be_s[128];
    __shared__ int s_src[64], s_dst[64];

    const int tid = threadIdx.x;
    const long base = (long)blockIdx.x * 64;

#pragma unroll
    for (int i = 0; i < 4; i++) {
        int f4 = tid + i * 256;
        ((float4*)we_s)[f4] = ((const float4*)We)[f4];
    }
    if (tid < 128) be_s[tid] = be[tid];
    if (tid < 64)       s_src[tid]      = src[base + tid];
    else if (tid < 128) s_dst[tid - 64] = dst[base + tid - 64];

#pragma unroll
    for (int i = 0; i < 2; i++) {
        int f4 = tid + i * 256;                       // 512 float4 total
        float4 v = ((const float4*)ef)[base * 8 + f4];
        int e = f4 >> 3;
        int k4 = (f4 & 7) * 4;
        ef_s[e * 33 + k4 + 0] = pack_dup(v.x);
        ef_s[e * 33 + k4 + 1] = pack_dup(v.y);
        ef_s[e * 33 + k4 + 2] = pack_dup(v.z);
        ef_s[e * 33 + k4 + 3] = pack_dup(v.w);
    }
    __syncthreads();

    const int eg = tid >> 3;        // 0..31 -> 2 edges each
    const int cg = tid & 7;         // 0..7  -> 16 strided cols
    const int e0 = eg * 2;

    unsigned long long acc[2][8];
#pragma unroll
    for (int i = 0; i < 2; i++)
#pragma unroll
        for (int j = 0; j < 8; j++) acc[i][j] = 0ULL;

#pragma unroll
    for (int k = 0; k < 32; k++) {
        unsigned long long ea = ef_s[e0 * 33 + k];
        unsigned long long eb = ef_s[(e0 + 1) * 33 + k];
#pragma unroll
        for (int g = 0; g < 4; g++) {
            ulonglong2 w = *(const ulonglong2*)(we_s + k * 128 + 4 * (cg + 8 * g));
            fma2(acc[0][2 * g],     ea, w.x);
            fma2(acc[0][2 * g + 1], ea, w.y);
            fma2(acc[1][2 * g],     eb, w.x);
            fma2(acc[1][2 * g + 1], eb, w.y);
        }
    }

#pragma unroll
    for (int i = 0; i < 2; i++) {
        int e = e0 + i;
        size_t srow = (size_t)s_src[e] * 128;
        size_t drow = (size_t)s_dst[e] * 128;
#pragma unroll
        for (int g = 0; g < 4; g++) {
            int cb = 4 * (cg + 8 * g);
            float4 xv = *(const float4*)(xin + srow + cb);
            float2 fa = unpk(acc[i][2 * g]);
            float2 fb = unpk(acc[i][2 * g + 1]);
            float4 m;
            m.x = fmaxf(xv.x + fa.x + be_s[cb + 0], 0.f);
            m.y = fmaxf(xv.y + fa.y + be_s[cb + 1], 0.f);
            m.z = fmaxf(xv.z + fb.x + be_s[cb + 2], 0.f);
            m.w = fmaxf(xv.w + fb.y + be_s[cb + 3], 0.f);
            red_add_v4(agg + drow + cb, m);
        }
    }
}

// ---------------- node GEMM v2: cp.async double-buffered pipeline -------------
// out = act(A @ W + b). Cin = 128 fixed. Raw smem tiles (cp.async-able):
//   A tile [node][16k] padded rows (20 floats), W tile [k][COUT] raw.
// Thread = NPT nodes (dup-packed scalar) x 16 cols (8 natural f32x2 pairs,
// strided by 2G so warp LDS.64 hits distinct banks).
template <int COUT, int NPT, int ACT>
__global__ void __launch_bounds__(256, 2)
gemm2(const float* __restrict__ A, const float* __restrict__ W,
      const float* __restrict__ bias,
      float* __restrict__ out, float* __restrict__ out2, int nrows) {
    constexpr int G     = COUT / 16;           // col groups per 256 threads
    constexpr int BN    = (256 / G) * NPT;     // nodes per block
    constexpr int AS    = 20;                  // padded A row stride (floats)
    constexpr int TILES = 8;                   // K=128 / 16

    __shared__ float a_s[2][BN * AS];
    __shared__ float w_s[2][16 * COUT];
    __shared__ float b_s[COUT];

    const int tid = threadIdx.x;
    const int nbase = blockIdx.x * BN;
    if (tid < COUT) b_s[tid] = bias[tid];

    const int cg = tid % G;
    const int ng = tid / G;
    const int n0 = ng * NPT;

    const uint32_t a_base = smem_u32(&a_s[0][0]);
    const uint32_t w_base = smem_u32(&w_s[0][0]);

    auto issue_tile = [&](int t) {
        const int buf = t & 1;
        const uint32_t ab = a_base + buf * (BN * AS * 4);
        const uint32_t wb = w_base + buf * (16 * COUT * 4);
        // A: BN*4 16B-chunks
#pragma unroll
        for (int i = 0; i < BN * 4 / 256; i++) {
            int id = tid + i * 256;
            int node = id >> 2, ch = id & 3;
            int row = nbase + node;
            if (row >= nrows) row = nrows - 1;   // clamp (results discarded)
            cp_async16(ab + (node * AS + ch * 4) * 4,
                       A + (size_t)row * 128 + t * 16 + ch * 4);
        }
        // W: 16*COUT/4 16B-chunks, fully contiguous
#pragma unroll
        for (int i = 0; i < (16 * COUT / 4) / 256; i++) {
            int c4 = tid + i * 256;
            cp_async16(wb + c4 * 16, W + (size_t)t * 16 * COUT + c4 * 4);
        }
        cp_commit();
    };

    unsigned long long acc[NPT][8];
#pragma unroll
    for (int n = 0; n < NPT; n++)
#pragma unroll
        for (int j = 0; j < 8; j++) acc[n][j] = 0ULL;

    issue_tile(0);
    issue_tile(1);

#pragma unroll 1
    for (int t = 0; t < TILES; t++) {
        if (t == TILES - 1) cp_wait0(); else cp_wait1();
        __syncthreads();
        const float* ab = &a_s[t & 1][0];
        const float* wb = &w_s[t & 1][0];

#pragma unroll
        for (int kq = 0; kq < 4; kq++) {
            float4 aq[NPT];
#pragma unroll
            for (int n = 0; n < NPT; n++)
                aq[n] = *(const float4*)(ab + (n0 + n) * AS + kq * 4);
#pragma unroll
            for (int kk = 0; kk < 4; kk++) {
                const int k = kq * 4 + kk;
                unsigned long long wv[8];
#pragma unroll
                for (int j = 0; j < 8; j++)
                    wv[j] = *(const unsigned long long*)
                                (wb + k * COUT + 2 * cg + 2 * G * j);
#pragma unroll
                for (int n = 0; n < NPT; n++) {
                    float av = (kk == 0) ? aq[n].x : (kk == 1) ? aq[n].y
                             : (kk == 2) ? aq[n].z : aq[n].w;
                    unsigned long long ad = pack_dup(av);
#pragma unroll
                    for (int j = 0; j < 8; j++) fma2(acc[n][j], ad, wv[j]);
                }
            }
        }
        __syncthreads();
        if (t + 2 < TILES) issue_tile(t + 2);
    }

    // Epilogue
#pragma unroll
    for (int n = 0; n < NPT; n++) {
        int row = nbase + n0 + n;
        if (row < nrows) {
#pragma unroll
            for (int j = 0; j < 8; j++) {
                int col = 2 * cg + 2 * G * j;
                float2 f = unpk(acc[n][j]);
                float v0 = f.x + b_s[col];
                float v1 = f.y + b_s[col + 1];
                if (ACT == 1) { v0 = fmaxf(v0, 0.f); v1 = fmaxf(v1, 0.f); }
                if (ACT == 2) { v0 = tanhf(v0);      v1 = tanhf(v1); }
                *(float2*)(out + (size_t)row * COUT + col) = make_float2(v0, v1);
                if (out2)
                    *(float2*)(out2 + (size_t)row * COUT + col) = make_float2(v0, v1);
            }
        }
    }
}

// ---------------- launch ------------------------------------------------------
extern "C" void kernel_launch(void* const* d_in, const int* in_sizes, int n_in,
                              void* d_out, int out_size) {
    const float* x    = (const float*)d_in[0];
    const int*   ei   = (const int*)d_in[1];
    const float* ef   = (const float*)d_in[2];
    const float* We1  = (const float*)d_in[3];
    const float* be1  = (const float*)d_in[4];
    const float* W1a  = (const float*)d_in[5];
    const float* b1a  = (const float*)d_in[6];
    const float* W1b  = (const float*)d_in[7];
    const float* b1b  = (const float*)d_in[8];
    const float* We2  = (const float*)d_in[9];
    const float* be2  = (const float*)d_in[10];
    const float* W2a  = (const float*)d_in[11];
    const float* b2a  = (const float*)d_in[12];
    const float* W2b  = (const float*)d_in[13];
    const float* b2b  = (const float*)d_in[14];
    const float* Wfc1 = (const float*)d_in[15];
    const float* bfc1 = (const float*)d_in[16];
    const float* Wfc2 = (const float*)d_in[17];
    const float* bfc2 = (const float*)d_in[18];
    float* out = (float*)d_out;

    float *agg, *t, *h;
    cudaGetSymbolAddress((void**)&agg, g_agg);
    cudaGetSymbolAddress((void**)&t,   g_t);
    cudaGetSymbolAddress((void**)&h,   g_h);

    const int* srcp = ei;
    const int* dstp = ei + Ee;

    const int n4 = Nn * 128 / 4;                 // 3,200,000
    const int cpG = (n4 + 255) / 256;            // 12500
    const int egG = Ee / 64;                     // 9375
    const int g128 = (Nn + 127) / 128;           // 782

    // Layer 1: agg = x + sum relu(x[src] + ef@We1 + be1)
    copy_kernel<<<cpG, 256>>>((float4*)agg, (const float4*)x, n4);
    edge_kernel<<<egG, 256>>>(x, srcp, dstp, ef, We1, be1, agg);
    gemm2<128, 4, 1><<<g128, 256>>>(agg, W1a, b1a, t, nullptr, Nn);
    gemm2<128, 4, 2><<<g128, 256>>>(t, W1b, b1b, h, agg, Nn);  // h=tanh(.), agg=h

    // Layer 2
    edge_kernel<<<egG, 256>>>(h, srcp, dstp, ef, We2, be2, agg);
    gemm2<128, 4, 1><<<g128, 256>>>(agg, W2a, b2a, t, nullptr, Nn);
    gemm2<128, 4, 2><<<g128, 256>>>(t, W2b, b2b, h, nullptr, Nn);

    // Head
    gemm2<128, 4, 2><<<g128, 256>>>(h, Wfc1, bfc1, t, nullptr, Nn);
    gemm2<64, 2, 0><<<g128, 256>>>(t, Wfc2, bfc2, out, nullptr, Nn);
}

// round 4
// speedup vs baseline: 1.4262x; 1.2814x over previous
#include <cuda_runtime.h>
#include <cuda_bf16.h>
#include <cstdint>

#define Nn 100000
#define Ee 600000

// ---------------- scratch (allocation-free: __device__ globals) --------------
__device__ float g_agg[Nn * 128];
__device__ float g_t[Nn * 128];
__device__ float g_h[Nn * 128];
// pre-transposed bf16 hi/lo weights, [n][136] padded rows: 6 matrices x {hi,lo}
__device__ __nv_bfloat16 g_wb[6][2][128 * 136];

// ---------------- helpers -----------------------------------------------------
__device__ __forceinline__ unsigned long long pack_dup(float v) {
    unsigned long long r;
    asm("mov.b64 %0, {%1, %1};" : "=l"(r) : "f"(v));
    return r;
}
__device__ __forceinline__ void fma2(unsigned long long& acc,
                                     unsigned long long a,
                                     unsigned long long b) {
    asm("fma.rn.f32x2 %0, %1, %2, %0;" : "+l"(acc) : "l"(a), "l"(b));
}
__device__ __forceinline__ float2 unpk(unsigned long long v) {
    float2 f;
    asm("mov.b64 {%0, %1}, %2;" : "=f"(f.x), "=f"(f.y) : "l"(v));
    return f;
}
__device__ __forceinline__ void red_add_v4(float* p, float4 v) {
    asm volatile("red.global.add.v4.f32 [%0], {%1, %2, %3, %4};"
                 :: "l"(p), "f"(v.x), "f"(v.y), "f"(v.z), "f"(v.w)
                 : "memory");
}
__device__ __forceinline__ uint32_t smem_u32(const void* p) {
    return (uint32_t)__cvta_generic_to_shared(p);
}
__device__ __forceinline__ void cp_async16(uint32_t dst, const void* src) {
    asm volatile("cp.async.cg.shared.global [%0], [%1], 16;"
                 :: "r"(dst), "l"(src));
}
__device__ __forceinline__ void cp_commit() {
    asm volatile("cp.async.commit_group;");
}
__device__ __forceinline__ void cp_wait0() {
    asm volatile("cp.async.wait_group 0;" ::: "memory");
}
__device__ __forceinline__ void ldx4(uint32_t* r, uint32_t addr) {
    asm volatile("ldmatrix.sync.aligned.m8n8.x4.shared.b16 {%0, %1, %2, %3}, [%4];"
                 : "=r"(r[0]), "=r"(r[1]), "=r"(r[2]), "=r"(r[3]) : "r"(addr));
}
__device__ __forceinline__ void mma_bf16(float* c, const uint32_t* a,
                                         const uint32_t* b) {
    asm volatile("mma.sync.aligned.m16n8k16.row.col.f32.bf16.bf16.f32 "
                 "{%0, %1, %2, %3}, {%4, %5, %6, %7}, {%8, %9}, {%0, %1, %2, %3};"
                 : "+f"(c[0]), "+f"(c[1]), "+f"(c[2]), "+f"(c[3])
                 : "r"(a[0]), "r"(a[1]), "r"(a[2]), "r"(a[3]),
                   "r"(b[0]), "r"(b[1]));
}
__device__ __forceinline__ uint32_t bf2_u32(__nv_bfloat162 x) {
    uint32_t r;
    memcpy(&r, &x, 4);
    return r;
}

// ---------------- init copy ---------------------------------------------------
__global__ void __launch_bounds__(256) copy_kernel(float4* __restrict__ dst,
                                                   const float4* __restrict__ src,
                                                   int n4) {
    int i = blockIdx.x * blockDim.x + threadIdx.x;
    if (i < n4) dst[i] = src[i];
}

// ---------------- weight prep: transpose + bf16 hi/lo split -------------------
__global__ void __launch_bounds__(256)
prep_wb(const float* __restrict__ W, __nv_bfloat16* __restrict__ hi,
        __nv_bfloat16* __restrict__ lo, int cout) {
    int id = blockIdx.x * 256 + threadIdx.x;
    if (id >= cout * 128) return;
    int n = id >> 7, k = id & 127;           // Bt[n][k] = W[k][n]
    float v = W[k * cout + n];
    __nv_bfloat16 h = __float2bfloat16_rn(v);
    __nv_bfloat16 l = __float2bfloat16_rn(v - __bfloat162float(h));
    hi[n * 136 + k] = h;
    lo[n * 136 + k] = l;
}

// ---------------- fused edge kernel (unchanged) -------------------------------
__global__ void __launch_bounds__(256, 3)
edge_kernel(const float* __restrict__ xin,
            const int* __restrict__ src, const int* __restrict__ dst,
            const float* __restrict__ ef,
            const float* __restrict__ We, const float* __restrict__ be,
            float* __restrict__ agg) {
    __shared__ float we_s[32 * 128];
    __shared__ unsigned long long ef_s[64 * 33];
    __shared__ float be_s[128];
    __shared__ int s_src[64], s_dst[64];

    const int tid = threadIdx.x;
    const long base = (long)blockIdx.x * 64;

#pragma unroll
    for (int i = 0; i < 4; i++) {
        int f4 = tid + i * 256;
        ((float4*)we_s)[f4] = ((const float4*)We)[f4];
    }
    if (tid < 128) be_s[tid] = be[tid];
    if (tid < 64)       s_src[tid]      = src[base + tid];
    else if (tid < 128) s_dst[tid - 64] = dst[base + tid - 64];

#pragma unroll
    for (int i = 0; i < 2; i++) {
        int f4 = tid + i * 256;
        float4 v = ((const float4*)ef)[base * 8 + f4];
        int e = f4 >> 3;
        int k4 = (f4 & 7) * 4;
        ef_s[e * 33 + k4 + 0] = pack_dup(v.x);
        ef_s[e * 33 + k4 + 1] = pack_dup(v.y);
        ef_s[e * 33 + k4 + 2] = pack_dup(v.z);
        ef_s[e * 33 + k4 + 3] = pack_dup(v.w);
    }
    __syncthreads();

    const int eg = tid >> 3;
    const int cg = tid & 7;
    const int e0 = eg * 2;

    unsigned long long acc[2][8];
#pragma unroll
    for (int i = 0; i < 2; i++)
#pragma unroll
        for (int j = 0; j < 8; j++) acc[i][j] = 0ULL;

#pragma unroll
    for (int k = 0; k < 32; k++) {
        unsigned long long ea = ef_s[e0 * 33 + k];
        unsigned long long eb = ef_s[(e0 + 1) * 33 + k];
#pragma unroll
        for (int g = 0; g < 4; g++) {
            ulonglong2 w = *(const ulonglong2*)(we_s + k * 128 + 4 * (cg + 8 * g));
            fma2(acc[0][2 * g],     ea, w.x);
            fma2(acc[0][2 * g + 1], ea, w.y);
            fma2(acc[1][2 * g],     eb, w.x);
            fma2(acc[1][2 * g + 1], eb, w.y);
        }
    }

#pragma unroll
    for (int i = 0; i < 2; i++) {
        int e = e0 + i;
        size_t srow = (size_t)s_src[e] * 128;
        size_t drow = (size_t)s_dst[e] * 128;
#pragma unroll
        for (int g = 0; g < 4; g++) {
            int cb = 4 * (cg + 8 * g);
            float4 xv = *(const float4*)(xin + srow + cb);
            float2 fa = unpk(acc[i][2 * g]);
            float2 fb = unpk(acc[i][2 * g + 1]);
            float4 m;
            m.x = fmaxf(xv.x + fa.x + be_s[cb + 0], 0.f);
            m.y = fmaxf(xv.y + fa.y + be_s[cb + 1], 0.f);
            m.z = fmaxf(xv.z + fb.x + be_s[cb + 2], 0.f);
            m.w = fmaxf(xv.w + fb.y + be_s[cb + 3], 0.f);
            red_add_v4(agg + drow + cb, m);
        }
    }
}

// ---------------- mma.sync bf16 3-term node GEMM ------------------------------
// out = act(A @ W + b). Block: 128 thr (4 warps), tile M=64 x COUT, K=128.
// A fp32 -> bf16 hi/lo smem; W pre-split bf16 hi/lo via cp.async.
// Warp w computes [64 x NW] (NW=COUT/4): 4 m-frags x NF n-frags per k-step.
template <int COUT, int ACT>
__global__ void __launch_bounds__(128, 2)
mgemm(const float* __restrict__ A, const __nv_bfloat16* __restrict__ Whi,
      const __nv_bfloat16* __restrict__ Wlo, const float* __restrict__ bias,
      float* __restrict__ out, float* __restrict__ out2, int nrows) {
    constexpr int NW = COUT / 4;              // warp n-width (32 or 16)
    constexpr int NF = NW / 8;                // n-frags per warp (4 or 2)
    constexpr uint32_t ABYTES = 64 * 136 * 2; // 17408
    constexpr uint32_t WBYTES = (uint32_t)COUT * 136 * 2;

    extern __shared__ char sm[];
    const uint32_t s0   = smem_u32(sm);
    const uint32_t sAhi = s0;
    const uint32_t sAlo = s0 + ABYTES;
    const uint32_t sWhi = s0 + 2 * ABYTES;
    const uint32_t sWlo = sWhi + WBYTES;

    const int tid  = threadIdx.x;
    const int wid  = tid >> 5;
    const int lane = tid & 31;
    const int mbase = blockIdx.x * 64;

    // W tiles: identical global/smem layout -> raw cp.async
    constexpr int WCH = (int)(WBYTES / 16);
    for (int i = tid; i < WCH; i += 128) {
        cp_async16(sWhi + i * 16, (const char*)Whi + i * 16);
        cp_async16(sWlo + i * 16, (const char*)Wlo + i * 16);
    }
    cp_commit();

    // A tile: load fp32, split to bf16 hi/lo, store swiveled rows (pitch 136)
    {
        const int row = tid >> 1, half = tid & 1;
        int grow = mbase + row;
        if (grow >= nrows) grow = nrows - 1;
        const float* ap = A + (size_t)grow * 128 + half * 64;
        const uint32_t d = row * 272 + half * 128;
#pragma unroll
        for (int i = 0; i < 8; i++) {
            float4 v0 = *(const float4*)(ap + i * 8);
            float4 v1 = *(const float4*)(ap + i * 8 + 4);
            __nv_bfloat162 h0 = __floats2bfloat162_rn(v0.x, v0.y);
            __nv_bfloat162 h1 = __floats2bfloat162_rn(v0.z, v0.w);
            __nv_bfloat162 h2 = __floats2bfloat162_rn(v1.x, v1.y);
            __nv_bfloat162 h3 = __floats2bfloat162_rn(v1.z, v1.w);
            __nv_bfloat162 l0 = __floats2bfloat162_rn(
                v0.x - __bfloat162float(h0.x), v0.y - __bfloat162float(h0.y));
            __nv_bfloat162 l1 = __floats2bfloat162_rn(
                v0.z - __bfloat162float(h1.x), v0.w - __bfloat162float(h1.y));
            __nv_bfloat162 l2 = __floats2bfloat162_rn(
                v1.x - __bfloat162float(h2.x), v1.y - __bfloat162float(h2.y));
            __nv_bfloat162 l3 = __floats2bfloat162_rn(
                v1.z - __bfloat162float(h3.x), v1.w - __bfloat162float(h3.y));
            asm volatile("st.shared.v4.b32 [%0], {%1, %2, %3, %4};"
                         :: "r"(sAhi + d + i * 16), "r"(bf2_u32(h0)),
                            "r"(bf2_u32(h1)), "r"(bf2_u32(h2)), "r"(bf2_u32(h3)));
            asm volatile("st.shared.v4.b32 [%0], {%1, %2, %3, %4};"
                         :: "r"(sAlo + d + i * 16), "r"(bf2_u32(l0)),
                            "r"(bf2_u32(l1)), "r"(bf2_u32(l2)), "r"(bf2_u32(l3)));
        }
    }
    cp_wait0();
    __syncthreads();

    // fragment lane addressing
    const uint32_t aoff = (uint32_t)(lane & 15) * 272 + ((lane >> 4) ? 16 : 0);
    const int brow = (lane & 7) + ((lane >> 4) << 3);
    const uint32_t boff = (uint32_t)(wid * NW + brow) * 272 + ((lane & 8) ? 16 : 0);

    float acc[4][NF][4];
#pragma unroll
    for (int mi = 0; mi < 4; mi++)
#pragma unroll
        for (int ni = 0; ni < NF; ni++)
#pragma unroll
            for (int q = 0; q < 4; q++) acc[mi][ni][q] = 0.f;

#pragma unroll
    for (int ks = 0; ks < 8; ks++) {
        uint32_t ah[4][4], al[4][4], bh[NF][2], bl[NF][2];
#pragma unroll
        for (int mi = 0; mi < 4; mi++) {
            ldx4(ah[mi], sAhi + aoff + mi * (16 * 272) + ks * 32);
            ldx4(al[mi], sAlo + aoff + mi * (16 * 272) + ks * 32);
        }
#pragma unroll
        for (int np = 0; np < NF / 2; np++) {
            uint32_t r[4];
            ldx4(r, sWhi + boff + np * (16 * 272) + ks * 32);
            bh[np * 2][0] = r[0]; bh[np * 2][1] = r[1];
            bh[np * 2 + 1][0] = r[2]; bh[np * 2 + 1][1] = r[3];
            ldx4(r, sWlo + boff + np * (16 * 272) + ks * 32);
            bl[np * 2][0] = r[0]; bl[np * 2][1] = r[1];
            bl[np * 2 + 1][0] = r[2]; bl[np * 2 + 1][1] = r[3];
        }
#pragma unroll
        for (int mi = 0; mi < 4; mi++)
#pragma unroll
            for (int ni = 0; ni < NF; ni++) {
                mma_bf16(acc[mi][ni], ah[mi], bh[ni]);
                mma_bf16(acc[mi][ni], ah[mi], bl[ni]);
                mma_bf16(acc[mi][ni], al[mi], bh[ni]);
            }
    }

    // epilogue
    const int g = lane >> 2, tq = lane & 3;
#pragma unroll
    for (int mi = 0; mi < 4; mi++) {
        const int r0 = mbase + mi * 16 + g;
#pragma unroll
        for (int ni = 0; ni < NF; ni++) {
            const int col = wid * NW + ni * 8 + tq * 2;
            float2 b = *(const float2*)(bias + col);
            float v0 = acc[mi][ni][0] + b.x;
            float v1 = acc[mi][ni][1] + b.y;
            float v2 = acc[mi][ni][2] + b.x;
            float v3 = acc[mi][ni][3] + b.y;
            if (ACT == 1) {
                v0 = fmaxf(v0, 0.f); v1 = fmaxf(v1, 0.f);
                v2 = fmaxf(v2, 0.f); v3 = fmaxf(v3, 0.f);
            }
            if (ACT == 2) {
                v0 = tanhf(v0); v1 = tanhf(v1);
                v2 = tanhf(v2); v3 = tanhf(v3);
            }
            if (r0 < nrows) {
                *(float2*)(out + (size_t)r0 * COUT + col) = make_float2(v0, v1);
                if (out2)
                    *(float2*)(out2 + (size_t)r0 * COUT + col) = make_float2(v0, v1);
            }
            if (r0 + 8 < nrows) {
                *(float2*)(out + (size_t)(r0 + 8) * COUT + col) = make_float2(v2, v3);
                if (out2)
                    *(float2*)(out2 + (size_t)(r0 + 8) * COUT + col) = make_float2(v2, v3);
            }
        }
    }
}

// ---------------- launch ------------------------------------------------------
extern "C" void kernel_launch(void* const* d_in, const int* in_sizes, int n_in,
                              void* d_out, int out_size) {
    const float* x    = (const float*)d_in[0];
    const int*   ei   = (const int*)d_in[1];
    const float* ef   = (const float*)d_in[2];
    const float* We1  = (const float*)d_in[3];
    const float* be1  = (const float*)d_in[4];
    const float* W1a  = (const float*)d_in[5];
    const float* b1a  = (const float*)d_in[6];
    const float* W1b  = (const float*)d_in[7];
    const float* b1b  = (const float*)d_in[8];
    const float* We2  = (const float*)d_in[9];
    const float* be2  = (const float*)d_in[10];
    const float* W2a  = (const float*)d_in[11];
    const float* b2a  = (const float*)d_in[12];
    const float* W2b  = (const float*)d_in[13];
    const float* b2b  = (const float*)d_in[14];
    const float* Wfc1 = (const float*)d_in[15];
    const float* bfc1 = (const float*)d_in[16];
    const float* Wfc2 = (const float*)d_in[17];
    const float* bfc2 = (const float*)d_in[18];
    float* out = (float*)d_out;

    float *agg, *t, *h;
    __nv_bfloat16* wb;
    cudaGetSymbolAddress((void**)&agg, g_agg);
    cudaGetSymbolAddress((void**)&t,   g_t);
    cudaGetSymbolAddress((void**)&h,   g_h);
    cudaGetSymbolAddress((void**)&wb,  g_wb);
    auto WB = [&](int m, int s) { return wb + ((size_t)m * 2 + s) * 128 * 136; };

    const int* srcp = ei;
    const int* dstp = ei + Ee;

    const int n4 = Nn * 128 / 4;
    const int cpG = (n4 + 255) / 256;
    const int egG = Ee / 64;
    const int gM = (Nn + 63) / 64;               // 1563

    constexpr int SM128 = 2 * 17408 + 2 * 128 * 136 * 2;  // 104448
    constexpr int SM64  = 2 * 17408 + 2 * 64 * 136 * 2;   // 69632
    cudaFuncSetAttribute(mgemm<128, 1>, cudaFuncAttributeMaxDynamicSharedMemorySize, SM128);
    cudaFuncSetAttribute(mgemm<128, 2>, cudaFuncAttributeMaxDynamicSharedMemorySize, SM128);
    cudaFuncSetAttribute(mgemm<64, 0>,  cudaFuncAttributeMaxDynamicSharedMemorySize, SM64);

    // weight prep (transpose + bf16 hi/lo split)
    prep_wb<<<64, 256>>>(W1a,  WB(0, 0), WB(0, 1), 128);
    prep_wb<<<64, 256>>>(W1b,  WB(1, 0), WB(1, 1), 128);
    prep_wb<<<64, 256>>>(W2a,  WB(2, 0), WB(2, 1), 128);
    prep_wb<<<64, 256>>>(W2b,  WB(3, 0), WB(3, 1), 128);
    prep_wb<<<64, 256>>>(Wfc1, WB(4, 0), WB(4, 1), 128);
    prep_wb<<<32, 256>>>(Wfc2, WB(5, 0), WB(5, 1), 64);

    // Layer 1: agg = x + sum relu(x[src] + ef@We1 + be1)
    copy_kernel<<<cpG, 256>>>((float4*)agg, (const float4*)x, n4);
    edge_kernel<<<egG, 256>>>(x, srcp, dstp, ef, We1, be1, agg);
    mgemm<128, 1><<<gM, 128, SM128>>>(agg, WB(0, 0), WB(0, 1), b1a, t, nullptr, Nn);
    mgemm<128, 2><<<gM, 128, SM128>>>(t, WB(1, 0), WB(1, 1), b1b, h, agg, Nn);

    // Layer 2
    edge_kernel<<<egG, 256>>>(h, srcp, dstp, ef, We2, be2, agg);
    mgemm<128, 1><<<gM, 128, SM128>>>(agg, WB(2, 0), WB(2, 1), b2a, t, nullptr, Nn);
    mgemm<128, 2><<<gM, 128, SM128>>>(t, WB(3, 0), WB(3, 1), b2b, h, nullptr, Nn);

    // Head
    mgemm<128, 2><<<gM, 128, SM128>>>(h, WB(4, 0), WB(4, 1), bfc1, t, nullptr, Nn);
    mgemm<64, 0><<<gM, 128, SM64>>>(t, WB(5, 0), WB(5, 1), bfc2, out, nullptr, Nn);
}

// round 5
// speedup vs baseline: 1.6385x; 1.1488x over previous
#include <cuda_runtime.h>
#include <cuda_bf16.h>
#include <cstdint>

#define Nn 100000
#define Ee 600000

// ---------------- scratch (allocation-free: __device__ globals) --------------
__device__ float g_agg[Nn * 128];
__device__ float g_t[Nn * 128];
__device__ float g_h[Nn * 128];
// pre-transposed bf16 hi/lo node weights, [n][136] pitch: 6 matrices x {hi,lo}
__device__ __nv_bfloat16 g_wb[6][2][128 * 136];
// pre-transposed bf16 hi/lo edge weights, [n][40] pitch: 2 matrices x {hi,lo}
__device__ __nv_bfloat16 g_web[2][2][128 * 40];

// ---------------- helpers -----------------------------------------------------
__device__ __forceinline__ void red_add_v2(float* p, float2 v) {
    asm volatile("red.global.add.v2.f32 [%0], {%1, %2};"
                 :: "l"(p), "f"(v.x), "f"(v.y) : "memory");
}
__device__ __forceinline__ uint32_t smem_u32(const void* p) {
    return (uint32_t)__cvta_generic_to_shared(p);
}
__device__ __forceinline__ void cp_async16(uint32_t dst, const void* src) {
    asm volatile("cp.async.cg.shared.global [%0], [%1], 16;"
                 :: "r"(dst), "l"(src));
}
__device__ __forceinline__ void cp_commit() {
    asm volatile("cp.async.commit_group;");
}
__device__ __forceinline__ void cp_wait0() {
    asm volatile("cp.async.wait_group 0;" ::: "memory");
}
__device__ __forceinline__ void ldx4(uint32_t* r, uint32_t addr) {
    asm volatile("ldmatrix.sync.aligned.m8n8.x4.shared.b16 {%0, %1, %2, %3}, [%4];"
                 : "=r"(r[0]), "=r"(r[1]), "=r"(r[2]), "=r"(r[3]) : "r"(addr));
}
__device__ __forceinline__ void mma_bf16(float* c, const uint32_t* a,
                                         const uint32_t* b) {
    asm volatile("mma.sync.aligned.m16n8k16.row.col.f32.bf16.bf16.f32 "
                 "{%0, %1, %2, %3}, {%4, %5, %6, %7}, {%8, %9}, {%0, %1, %2, %3};"
                 : "+f"(c[0]), "+f"(c[1]), "+f"(c[2]), "+f"(c[3])
                 : "r"(a[0]), "r"(a[1]), "r"(a[2]), "r"(a[3]),
                   "r"(b[0]), "r"(b[1]));
}
__device__ __forceinline__ uint32_t bf2_u32(__nv_bfloat162 x) {
    uint32_t r;
    memcpy(&r, &x, 4);
    return r;
}

// ---------------- init copy ---------------------------------------------------
__global__ void __launch_bounds__(256) copy_kernel(float4* __restrict__ dst,
                                                   const float4* __restrict__ src,
                                                   int n4) {
    int i = blockIdx.x * blockDim.x + threadIdx.x;
    if (i < n4) dst[i] = src[i];
}

// ---------------- weight prep -------------------------------------------------
__global__ void __launch_bounds__(256)
prep_wb(const float* __restrict__ W, __nv_bfloat16* __restrict__ hi,
        __nv_bfloat16* __restrict__ lo, int cout) {
    int id = blockIdx.x * 256 + threadIdx.x;
    if (id >= cout * 128) return;
    int n = id >> 7, k = id & 127;           // Bt[n][k] = W[k][n]
    float v = W[k * cout + n];
    __nv_bfloat16 h = __float2bfloat16_rn(v);
    __nv_bfloat16 l = __float2bfloat16_rn(v - __bfloat162float(h));
    hi[n * 136 + k] = h;
    lo[n * 136 + k] = l;
}
// edge weights: We [32 x 128] -> WeT [128 n][40 pitch] hi/lo
__global__ void __launch_bounds__(256)
prep_wet(const float* __restrict__ We, __nv_bfloat16* __restrict__ hi,
         __nv_bfloat16* __restrict__ lo) {
    int id = blockIdx.x * 256 + threadIdx.x;
    if (id >= 128 * 32) return;
    int n = id >> 5, k = id & 31;
    float v = We[k * 128 + n];
    __nv_bfloat16 h = __float2bfloat16_rn(v);
    __nv_bfloat16 l = __float2bfloat16_rn(v - __bfloat162float(h));
    hi[n * 40 + k] = h;
    lo[n * 40 + k] = l;
}

// ---------------- HMMA fused edge kernel --------------------------------------
// Block: 256 thr (8 warps), 128 edges. warp w -> edges [16w,16w+16) x 128 cols.
// e = ef @ We (3-term bf16 HMMA); epilogue: relu(x[src]+e+be) -> red.add agg[dst].
__global__ void __launch_bounds__(256, 2)
edge_kernel(const float* __restrict__ xin,
            const int* __restrict__ src, const int* __restrict__ dst,
            const float* __restrict__ ef,
            const __nv_bfloat16* __restrict__ Weh,
            const __nv_bfloat16* __restrict__ Wel,
            const float* __restrict__ be,
            float* __restrict__ agg) {
    __shared__ __align__(16) __nv_bfloat16 sWeh[128 * 40], sWel[128 * 40];
    __shared__ __align__(16) __nv_bfloat16 sEfh[128 * 40], sEfl[128 * 40];
    __shared__ float sbias[128];
    __shared__ int ssrc[128], sdst[128];

    const int tid  = threadIdx.x;
    const int wid  = tid >> 5;
    const int lane = tid & 31;
    const int base = blockIdx.x * 128;
    const int nvalid = min(128, Ee - base);

    // We hi/lo: raw cp.async (global layout == smem layout), 640 chunks each
    const uint32_t swh = smem_u32(sWeh), swl = smem_u32(sWel);
    for (int i = tid; i < 640; i += 256) {
        cp_async16(swh + i * 16, (const char*)Weh + i * 16);
        cp_async16(swl + i * 16, (const char*)Wel + i * 16);
    }
    cp_commit();

    if (tid < 128) {
        sbias[tid] = be[tid];
        int e = min(base + tid, Ee - 1);
        ssrc[tid] = src[e];
        sdst[tid] = dst[e];
    }

    // ef tile: 128 edges x 32 k, fp32 -> bf16 hi/lo, pitch 40
    {
        const int edge = tid >> 1, half = tid & 1;
        int ge = min(base + edge, Ee - 1);
        const float4* ap = (const float4*)(ef + (size_t)ge * 32 + half * 16);
        const uint32_t dh = smem_u32(sEfh) + edge * 80 + half * 32;
        const uint32_t dl = smem_u32(sEfl) + edge * 80 + half * 32;
#pragma unroll
        for (int i = 0; i < 4; i++) {
            float4 v = ap[i];
            __nv_bfloat162 h0 = __floats2bfloat162_rn(v.x, v.y);
            __nv_bfloat162 h1 = __floats2bfloat162_rn(v.z, v.w);
            __nv_bfloat162 l0 = __floats2bfloat162_rn(
                v.x - __bfloat162float(h0.x), v.y - __bfloat162float(h0.y));
            __nv_bfloat162 l1 = __floats2bfloat162_rn(
                v.z - __bfloat162float(h1.x), v.w - __bfloat162float(h1.y));
            asm volatile("st.shared.v2.b32 [%0], {%1, %2};"
                         :: "r"(dh + i * 8), "r"(bf2_u32(h0)), "r"(bf2_u32(h1)));
            asm volatile("st.shared.v2.b32 [%0], {%1, %2};"
                         :: "r"(dl + i * 8), "r"(bf2_u32(l0)), "r"(bf2_u32(l1)));
        }
    }
    cp_wait0();
    __syncthreads();

    // fragment addressing (pitch 80B)
    const uint32_t aoff = smem_u32(sEfh)
        + (uint32_t)(wid * 16 + (lane & 15)) * 80 + ((lane >> 4) ? 16 : 0);
    const uint32_t aloff = aoff + (smem_u32(sEfl) - smem_u32(sEfh));
    const int brow = (lane & 7) + ((lane >> 4) << 3);
    const uint32_t boff = smem_u32(sWeh) + (uint32_t)brow * 80 + ((lane & 8) ? 16 : 0);
    const uint32_t bloff = boff + (smem_u32(sWel) - smem_u32(sWeh));

    float acc[16][4];
#pragma unroll
    for (int ni = 0; ni < 16; ni++)
#pragma unroll
        for (int q = 0; q < 4; q++) acc[ni][q] = 0.f;

#pragma unroll
    for (int ks = 0; ks < 2; ks++) {
        uint32_t ah[4], al[4];
        ldx4(ah, aoff + ks * 32);
        ldx4(al, aloff + ks * 32);
#pragma unroll
        for (int np = 0; np < 8; np++) {
            uint32_t rh[4], rl[4];
            ldx4(rh, boff + np * (16 * 80) + ks * 32);
            ldx4(rl, bloff + np * (16 * 80) + ks * 32);
            uint32_t bh0[2] = {rh[0], rh[1]}, bh1[2] = {rh[2], rh[3]};
            uint32_t bl0[2] = {rl[0], rl[1]}, bl1[2] = {rl[2], rl[3]};
            mma_bf16(acc[np * 2],     ah, bh0);
            mma_bf16(acc[np * 2],     ah, bl0);
            mma_bf16(acc[np * 2],     al, bh0);
            mma_bf16(acc[np * 2 + 1], ah, bh1);
            mma_bf16(acc[np * 2 + 1], ah, bl1);
            mma_bf16(acc[np * 2 + 1], al, bh1);
        }
    }

    // epilogue: per (row, nfrag): gather x[src], relu, red.add.v2 to agg[dst]
    const int g = lane >> 2, tq = lane & 3;
    const int er0 = wid * 16 + g;          // local edge rows er0, er0+8
#pragma unroll
    for (int half = 0; half < 2; half++) {
        const int er = er0 + half * 8;
        if (er < nvalid) {
            const size_t srow = (size_t)ssrc[er] * 128;
            const size_t drow = (size_t)sdst[er] * 128;
#pragma unroll
            for (int ni = 0; ni < 16; ni++) {
                const int col = ni * 8 + tq * 2;
                float2 xv = *(const float2*)(xin + srow + col);
                float2 m;
                m.x = fmaxf(xv.x + acc[ni][half * 2 + 0] + sbias[col], 0.f);
                m.y = fmaxf(xv.y + acc[ni][half * 2 + 1] + sbias[col + 1], 0.f);
                red_add_v2(agg + drow + col, m);
            }
        }
    }
}

// ---------------- persistent mma.sync bf16 3-term node GEMM -------------------
// out = act(A @ W + b). Block: 128 thr (4 warps). W resident; loop M-tiles of 64.
template <int COUT, int ACT>
__global__ void __launch_bounds__(128, 2)
mgemm(const float* __restrict__ A, const __nv_bfloat16* __restrict__ Whi,
      const __nv_bfloat16* __restrict__ Wlo, const float* __restrict__ bias,
      float* __restrict__ out, float* __restrict__ out2, int nrows, int ntiles) {
    constexpr int NW = COUT / 4;
    constexpr int NF = NW / 8;
    constexpr uint32_t ABYTES = 64 * 136 * 2;
    constexpr uint32_t WBYTES = (uint32_t)COUT * 136 * 2;

    extern __shared__ char sm[];
    const uint32_t s0   = smem_u32(sm);
    const uint32_t sAhi = s0;
    const uint32_t sAlo = s0 + ABYTES;
    const uint32_t sWhi = s0 + 2 * ABYTES;
    const uint32_t sWlo = sWhi + WBYTES;

    const int tid  = threadIdx.x;
    const int wid  = tid >> 5;
    const int lane = tid & 31;

    // W tiles: loaded ONCE per CTA
    constexpr int WCH = (int)(WBYTES / 16);
    for (int i = tid; i < WCH; i += 128) {
        cp_async16(sWhi + i * 16, (const char*)Whi + i * 16);
        cp_async16(sWlo + i * 16, (const char*)Wlo + i * 16);
    }
    cp_commit();

    const uint32_t aoff = (uint32_t)(lane & 15) * 272 + ((lane >> 4) ? 16 : 0);
    const int brow = (lane & 7) + ((lane >> 4) << 3);
    const uint32_t boff = (uint32_t)(wid * NW + brow) * 272 + ((lane & 8) ? 16 : 0);
    const int g = lane >> 2, tq = lane & 3;

    bool first = true;
    for (int mt = blockIdx.x; mt < ntiles; mt += gridDim.x) {
        const int mbase = mt * 64;

        // A tile: fp32 -> bf16 hi/lo, pitch 136
        {
            const int row = tid >> 1, half = tid & 1;
            int grow = mbase + row;
            if (grow >= nrows) grow = nrows - 1;
            const float* ap = A + (size_t)grow * 128 + half * 64;
            const uint32_t d = row * 272 + half * 128;
#pragma unroll
            for (int i = 0; i < 8; i++) {
                float4 v0 = *(const float4*)(ap + i * 8);
                float4 v1 = *(const float4*)(ap + i * 8 + 4);
                __nv_bfloat162 h0 = __floats2bfloat162_rn(v0.x, v0.y);
                __nv_bfloat162 h1 = __floats2bfloat162_rn(v0.z, v0.w);
                __nv_bfloat162 h2 = __floats2bfloat162_rn(v1.x, v1.y);
                __nv_bfloat162 h3 = __floats2bfloat162_rn(v1.z, v1.w);
                __nv_bfloat162 l0 = __floats2bfloat162_rn(
                    v0.x - __bfloat162float(h0.x), v0.y - __bfloat162float(h0.y));
                __nv_bfloat162 l1 = __floats2bfloat162_rn(
                    v0.z - __bfloat162float(h1.x), v0.w - __bfloat162float(h1.y));
                __nv_bfloat162 l2 = __floats2bfloat162_rn(
                    v1.x - __bfloat162float(h2.x), v1.y - __bfloat162float(h2.y));
                __nv_bfloat162 l3 = __floats2bfloat162_rn(
                    v1.z - __bfloat162float(h3.x), v1.w - __bfloat162float(h3.y));
                asm volatile("st.shared.v4.b32 [%0], {%1, %2, %3, %4};"
                             :: "r"(sAhi + d + i * 16), "r"(bf2_u32(h0)),
                                "r"(bf2_u32(h1)), "r"(bf2_u32(h2)), "r"(bf2_u32(h3)));
                asm volatile("st.shared.v4.b32 [%0], {%1, %2, %3, %4};"
                             :: "r"(sAlo + d + i * 16), "r"(bf2_u32(l0)),
                                "r"(bf2_u32(l1)), "r"(bf2_u32(l2)), "r"(bf2_u32(l3)));
            }
        }
        if (first) { cp_wait0(); first = false; }
        __syncthreads();

        float acc[4][NF][4];
#pragma unroll
        for (int mi = 0; mi < 4; mi++)
#pragma unroll
            for (int ni = 0; ni < NF; ni++)
#pragma unroll
                for (int q = 0; q < 4; q++) acc[mi][ni][q] = 0.f;

#pragma unroll
        for (int ks = 0; ks < 8; ks++) {
            uint32_t ah[4][4], al[4][4], bh[NF][2], bl[NF][2];
#pragma unroll
            for (int mi = 0; mi < 4; mi++) {
                ldx4(ah[mi], sAhi + aoff + mi * (16 * 272) + ks * 32);
                ldx4(al[mi], sAlo + aoff + mi * (16 * 272) + ks * 32);
            }
#pragma unroll
            for (int np = 0; np < NF / 2; np++) {
                uint32_t r[4];
                ldx4(r, sWhi + boff + np * (16 * 272) + ks * 32);
                bh[np * 2][0] = r[0]; bh[np * 2][1] = r[1];
                bh[np * 2 + 1][0] = r[2]; bh[np * 2 + 1][1] = r[3];
                ldx4(r, sWlo + boff + np * (16 * 272) + ks * 32);
                bl[np * 2][0] = r[0]; bl[np * 2][1] = r[1];
                bl[np * 2 + 1][0] = r[2]; bl[np * 2 + 1][1] = r[3];
            }
#pragma unroll
            for (int mi = 0; mi < 4; mi++)
#pragma unroll
                for (int ni = 0; ni < NF; ni++) {
                    mma_bf16(acc[mi][ni], ah[mi], bh[ni]);
                    mma_bf16(acc[mi][ni], ah[mi], bl[ni]);
                    mma_bf16(acc[mi][ni], al[mi], bh[ni]);
                }
        }
        __syncthreads();   // A smem free for next tile

        // epilogue (registers only)
#pragma unroll
        for (int mi = 0; mi < 4; mi++) {
            const int r0 = mbase + mi * 16 + g;
#pragma unroll
            for (int ni = 0; ni < NF; ni++) {
                const int col = wid * NW + ni * 8 + tq * 2;
                float2 b = *(const float2*)(bias + col);
                float v0 = acc[mi][ni][0] + b.x;
                float v1 = acc[mi][ni][1] + b.y;
                float v2 = acc[mi][ni][2] + b.x;
                float v3 = acc[mi][ni][3] + b.y;
                if (ACT == 1) {
                    v0 = fmaxf(v0, 0.f); v1 = fmaxf(v1, 0.f);
                    v2 = fmaxf(v2, 0.f); v3 = fmaxf(v3, 0.f);
                }
                if (ACT == 2) {
                    v0 = tanhf(v0); v1 = tanhf(v1);
                    v2 = tanhf(v2); v3 = tanhf(v3);
                }
                if (r0 < nrows) {
                    *(float2*)(out + (size_t)r0 * COUT + col) = make_float2(v0, v1);
                    if (out2)
                        *(float2*)(out2 + (size_t)r0 * COUT + col) = make_float2(v0, v1);
                }
                if (r0 + 8 < nrows) {
                    *(float2*)(out + (size_t)(r0 + 8) * COUT + col) = make_float2(v2, v3);
                    if (out2)
                        *(float2*)(out2 + (size_t)(r0 + 8) * COUT + col) = make_float2(v2, v3);
                }
            }
        }
    }
}

// ---------------- launch ------------------------------------------------------
extern "C" void kernel_launch(void* const* d_in, const int* in_sizes, int n_in,
                              void* d_out, int out_size) {
    const float* x    = (const float*)d_in[0];
    const int*   ei   = (const int*)d_in[1];
    const float* ef   = (const float*)d_in[2];
    const float* We1  = (const float*)d_in[3];
    const float* be1  = (const float*)d_in[4];
    const float* W1a  = (const float*)d_in[5];
    const float* b1a  = (const float*)d_in[6];
    const float* W1b  = (const float*)d_in[7];
    const float* b1b  = (const float*)d_in[8];
    const float* We2  = (const float*)d_in[9];
    const float* be2  = (const float*)d_in[10];
    const float* W2a  = (const float*)d_in[11];
    const float* b2a  = (const float*)d_in[12];
    const float* W2b  = (const float*)d_in[13];
    const float* b2b  = (const float*)d_in[14];
    const float* Wfc1 = (const float*)d_in[15];
    const float* bfc1 = (const float*)d_in[16];
    const float* Wfc2 = (const float*)d_in[17];
    const float* bfc2 = (const float*)d_in[18];
    float* out = (float*)d_out;

    float *agg, *t, *h;
    __nv_bfloat16 *wb, *web;
    cudaGetSymbolAddress((void**)&agg, g_agg);
    cudaGetSymbolAddress((void**)&t,   g_t);
    cudaGetSymbolAddress((void**)&h,   g_h);
    cudaGetSymbolAddress((void**)&wb,  g_wb);
    cudaGetSymbolAddress((void**)&web, g_web);
    auto WB = [&](int m, int s) { return wb + ((size_t)m * 2 + s) * 128 * 136; };
    auto WE = [&](int m, int s) { return web + ((size_t)m * 2 + s) * 128 * 40; };

    const int* srcp = ei;
    const int* dstp = ei + Ee;

    const int n4 = Nn * 128 / 4;
    const int cpG = (n4 + 255) / 256;
    const int egG = (Ee + 127) / 128;            // 4688
    const int ntiles = (Nn + 63) / 64;           // 1563
    const int gG = 296;                          // persistent: 2 CTAs/SM

    constexpr int SM128 = 2 * 17408 + 2 * 128 * 136 * 2;  // 104448
    constexpr int SM64  = 2 * 17408 + 2 * 64 * 136 * 2;   // 69632
    cudaFuncSetAttribute(mgemm<128, 1>, cudaFuncAttributeMaxDynamicSharedMemorySize, SM128);
    cudaFuncSetAttribute(mgemm<128, 2>, cudaFuncAttributeMaxDynamicSharedMemorySize, SM128);
    cudaFuncSetAttribute(mgemm<64, 0>,  cudaFuncAttributeMaxDynamicSharedMemorySize, SM64);

    // weight prep
    prep_wb<<<64, 256>>>(W1a,  WB(0, 0), WB(0, 1), 128);
    prep_wb<<<64, 256>>>(W1b,  WB(1, 0), WB(1, 1), 128);
    prep_wb<<<64, 256>>>(W2a,  WB(2, 0), WB(2, 1), 128);
    prep_wb<<<64, 256>>>(W2b,  WB(3, 0), WB(3, 1), 128);
    prep_wb<<<64, 256>>>(Wfc1, WB(4, 0), WB(4, 1), 128);
    prep_wb<<<32, 256>>>(Wfc2, WB(5, 0), WB(5, 1), 64);
    prep_wet<<<16, 256>>>(We1, WE(0, 0), WE(0, 1));
    prep_wet<<<16, 256>>>(We2, WE(1, 0), WE(1, 1));

    // Layer 1: agg = x + sum relu(x[src] + ef@We1 + be1)
    copy_kernel<<<cpG, 256>>>((float4*)agg, (const float4*)x, n4);
    edge_kernel<<<egG, 256>>>(x, srcp, dstp, ef, WE(0, 0), WE(0, 1), be1, agg);
    mgemm<128, 1><<<gG, 128, SM128>>>(agg, WB(0, 0), WB(0, 1), b1a, t, nullptr, Nn, ntiles);
    mgemm<128, 2><<<gG, 128, SM128>>>(t, WB(1, 0), WB(1, 1), b1b, h, agg, Nn, ntiles);

    // Layer 2
    edge_kernel<<<egG, 256>>>(h, srcp, dstp, ef, WE(1, 0), WE(1, 1), be2, agg);
    mgemm<128, 1><<<gG, 128, SM128>>>(agg, WB(2, 0), WB(2, 1), b2a, t, nullptr, Nn, ntiles);
    mgemm<128, 2><<<gG, 128, SM128>>>(t, WB(3, 0), WB(3, 1), b2b, h, nullptr, Nn, ntiles);

    // Head
    mgemm<128, 2><<<gG, 128, SM128>>>(h, WB(4, 0), WB(4, 1), bfc1, t, nullptr, Nn, ntiles);
    mgemm<64, 0><<<gG, 128, SM64>>>(t, WB(5, 0), WB(5, 1), bfc2, out, nullptr, Nn, ntiles);
}

// round 6
// speedup vs baseline: 1.6875x; 1.0299x over previous
#include <cuda_runtime.h>
#include <cuda_bf16.h>
#include <cstdint>

#define Nn 100000
#define Ee 600000

// ---------------- scratch (allocation-free: __device__ globals) --------------
__device__ float g_agg[Nn * 128];
__device__ float g_h[Nn * 128];
// pre-transposed bf16 hi/lo node weights, [n][136] pitch: 6 matrices x {hi,lo}
__device__ __nv_bfloat16 g_wb[6][2][128 * 136];
// pre-transposed bf16 hi/lo edge weights, [n][40] pitch: 2 matrices x {hi,lo}
__device__ __nv_bfloat16 g_web[2][2][128 * 40];

// ---------------- helpers -----------------------------------------------------
__device__ __forceinline__ void red_add_v2(float* p, float2 v) {
    asm volatile("red.global.add.v2.f32 [%0], {%1, %2};"
                 :: "l"(p), "f"(v.x), "f"(v.y) : "memory");
}
__device__ __forceinline__ uint32_t smem_u32(const void* p) {
    return (uint32_t)__cvta_generic_to_shared(p);
}
__device__ __forceinline__ void cp_async16(uint32_t dst, const void* src) {
    asm volatile("cp.async.cg.shared.global [%0], [%1], 16;"
                 :: "r"(dst), "l"(src));
}
__device__ __forceinline__ void cp_commit() {
    asm volatile("cp.async.commit_group;");
}
__device__ __forceinline__ void cp_wait0() {
    asm volatile("cp.async.wait_group 0;" ::: "memory");
}
__device__ __forceinline__ void ldx4(uint32_t* r, uint32_t addr) {
    asm volatile("ldmatrix.sync.aligned.m8n8.x4.shared.b16 {%0, %1, %2, %3}, [%4];"
                 : "=r"(r[0]), "=r"(r[1]), "=r"(r[2]), "=r"(r[3]) : "r"(addr));
}
__device__ __forceinline__ void mma_bf16(float* c, const uint32_t* a,
                                         const uint32_t* b) {
    asm volatile("mma.sync.aligned.m16n8k16.row.col.f32.bf16.bf16.f32 "
                 "{%0, %1, %2, %3}, {%4, %5, %6, %7}, {%8, %9}, {%0, %1, %2, %3};"
                 : "+f"(c[0]), "+f"(c[1]), "+f"(c[2]), "+f"(c[3])
                 : "r"(a[0]), "r"(a[1]), "r"(a[2]), "r"(a[3]),
                   "r"(b[0]), "r"(b[1]));
}
__device__ __forceinline__ uint32_t bf2_u32(__nv_bfloat162 x) {
    uint32_t r;
    memcpy(&r, &x, 4);
    return r;
}
__device__ __forceinline__ uint32_t split_hi2(float a, float b, uint32_t& lo) {
    __nv_bfloat162 h = __floats2bfloat162_rn(a, b);
    __nv_bfloat162 l = __floats2bfloat162_rn(a - __bfloat162float(h.x),
                                             b - __bfloat162float(h.y));
    lo = bf2_u32(l);
    return bf2_u32(h);
}

// ---------------- init copy ---------------------------------------------------
__global__ void __launch_bounds__(256) copy_kernel(float4* __restrict__ dst,
                                                   const float4* __restrict__ src,
                                                   int n4) {
    int i = blockIdx.x * blockDim.x + threadIdx.x;
    if (i < n4) dst[i] = src[i];
}

// ---------------- fused weight prep (ALL matrices, one launch) ----------------
__global__ void __launch_bounds__(256)
prep_all(const float* __restrict__ W1a, const float* __restrict__ W1b,
         const float* __restrict__ W2a, const float* __restrict__ W2b,
         const float* __restrict__ Wfc1, const float* __restrict__ Wfc2,
         const float* __restrict__ We1, const float* __restrict__ We2,
         __nv_bfloat16* __restrict__ wb, __nv_bfloat16* __restrict__ web) {
    int id = blockIdx.x * 256 + threadIdx.x;
    if (id < 81920) {                       // 5 square node matrices
        int m = id / 16384, e = id % 16384;
        const float* W = (m == 0) ? W1a : (m == 1) ? W1b
                       : (m == 2) ? W2a : (m == 3) ? W2b : Wfc1;
        int n = e >> 7, k = e & 127;
        float v = W[k * 128 + n];
        __nv_bfloat16 h = __float2bfloat16_rn(v);
        __nv_bfloat16 l = __float2bfloat16_rn(v - __bfloat162float(h));
        wb[(size_t)m * 2 * 128 * 136 + n * 136 + k] = h;
        wb[((size_t)m * 2 + 1) * 128 * 136 + n * 136 + k] = l;
    } else if (id < 90112) {                // Wfc2 (128 -> 64)
        int e = id - 81920;
        int n = e >> 7, k = e & 127;        // n in [0,64)
        float v = Wfc2[k * 64 + n];
        __nv_bfloat16 h = __float2bfloat16_rn(v);
        __nv_bfloat16 l = __float2bfloat16_rn(v - __bfloat162float(h));
        wb[(size_t)5 * 2 * 128 * 136 + n * 136 + k] = h;
        wb[((size_t)5 * 2 + 1) * 128 * 136 + n * 136 + k] = l;
    } else if (id < 98304) {                // edge weights (32 -> 128), 2x
        int e = id - 90112;
        int m = e >> 12; e &= 4095;
        int n = e >> 5, k = e & 31;
        const float* We = m ? We2 : We1;
        float v = We[k * 128 + n];
        __nv_bfloat16 h = __float2bfloat16_rn(v);
        __nv_bfloat16 l = __float2bfloat16_rn(v - __bfloat162float(h));
        web[(size_t)m * 2 * 128 * 40 + n * 40 + k] = h;
        web[((size_t)m * 2 + 1) * 128 * 40 + n * 40 + k] = l;
    }
}

// ---------------- HMMA fused edge kernel --------------------------------------
__global__ void __launch_bounds__(256, 2)
edge_kernel(const float* __restrict__ xin,
            const int* __restrict__ src, const int* __restrict__ dst,
            const float* __restrict__ ef,
            const __nv_bfloat16* __restrict__ Weh,
            const __nv_bfloat16* __restrict__ Wel,
            const float* __restrict__ be,
            float* __restrict__ agg) {
    __shared__ __align__(16) __nv_bfloat16 sWeh[128 * 40], sWel[128 * 40];
    __shared__ __align__(16) __nv_bfloat16 sEfh[128 * 40], sEfl[128 * 40];
    __shared__ float sbias[128];
    __shared__ int ssrc[128], sdst[128];

    const int tid  = threadIdx.x;
    const int wid  = tid >> 5;
    const int lane = tid & 31;
    const int base = blockIdx.x * 128;
    const int nvalid = min(128, Ee - base);

    const uint32_t swh = smem_u32(sWeh), swl = smem_u32(sWel);
    for (int i = tid; i < 640; i += 256) {
        cp_async16(swh + i * 16, (const char*)Weh + i * 16);
        cp_async16(swl + i * 16, (const char*)Wel + i * 16);
    }
    cp_commit();

    if (tid < 128) {
        sbias[tid] = be[tid];
        int e = min(base + tid, Ee - 1);
        ssrc[tid] = src[e];
        sdst[tid] = dst[e];
    }

    {
        const int edge = tid >> 1, half = tid & 1;
        int ge = min(base + edge, Ee - 1);
        const float4* ap = (const float4*)(ef + (size_t)ge * 32 + half * 16);
        const uint32_t dh = smem_u32(sEfh) + edge * 80 + half * 32;
        const uint32_t dl = smem_u32(sEfl) + edge * 80 + half * 32;
#pragma unroll
        for (int i = 0; i < 4; i++) {
            float4 v = ap[i];
            uint32_t l0, l1;
            uint32_t h0 = split_hi2(v.x, v.y, l0);
            uint32_t h1 = split_hi2(v.z, v.w, l1);
            asm volatile("st.shared.v2.b32 [%0], {%1, %2};"
                         :: "r"(dh + i * 8), "r"(h0), "r"(h1));
            asm volatile("st.shared.v2.b32 [%0], {%1, %2};"
                         :: "r"(dl + i * 8), "r"(l0), "r"(l1));
        }
    }
    cp_wait0();
    __syncthreads();

    const int g = lane >> 2, tq = lane & 3;
    const uint32_t aoff = smem_u32(sEfh)
        + (uint32_t)(wid * 16 + (lane & 15)) * 80 + ((lane >> 4) ? 16 : 0);
    const uint32_t aloff = aoff + (smem_u32(sEfl) - smem_u32(sEfh));
    const int brow = (lane & 7) + ((lane >> 4) << 3);
    const uint32_t boff = smem_u32(sWeh) + (uint32_t)brow * 80 + ((lane & 8) ? 16 : 0);
    const uint32_t bloff = boff + (smem_u32(sWel) - smem_u32(sWeh));

    // seed accumulators with bias (added exactly once per edge message)
    float acc[16][4];
#pragma unroll
    for (int ni = 0; ni < 16; ni++) {
        float2 b = *(const float2*)(sbias + ni * 8 + tq * 2);
        acc[ni][0] = b.x; acc[ni][1] = b.y;
        acc[ni][2] = b.x; acc[ni][3] = b.y;
    }

#pragma unroll
    for (int ks = 0; ks < 2; ks++) {
        uint32_t ah[4], al[4];
        ldx4(ah, aoff + ks * 32);
        ldx4(al, aloff + ks * 32);
#pragma unroll
        for (int np = 0; np < 8; np++) {
            uint32_t rh[4], rl[4];
            ldx4(rh, boff + np * (16 * 80) + ks * 32);
            ldx4(rl, bloff + np * (16 * 80) + ks * 32);
            uint32_t bh0[2] = {rh[0], rh[1]}, bh1[2] = {rh[2], rh[3]};
            uint32_t bl0[2] = {rl[0], rl[1]}, bl1[2] = {rl[2], rl[3]};
            mma_bf16(acc[np * 2],     ah, bh0);
            mma_bf16(acc[np * 2],     ah, bl0);
            mma_bf16(acc[np * 2],     al, bh0);
            mma_bf16(acc[np * 2 + 1], ah, bh1);
            mma_bf16(acc[np * 2 + 1], ah, bl1);
            mma_bf16(acc[np * 2 + 1], al, bh1);
        }
    }

    const int er0 = wid * 16 + g;
#pragma unroll
    for (int half = 0; half < 2; half++) {
        const int er = er0 + half * 8;
        if (er < nvalid) {
            const size_t srow = (size_t)ssrc[er] * 128;
            const size_t drow = (size_t)sdst[er] * 128;
#pragma unroll
            for (int ni = 0; ni < 16; ni++) {
                const int col = ni * 8 + tq * 2;
                float2 xv = *(const float2*)(xin + srow + col);
                float2 m;
                m.x = fmaxf(xv.x + acc[ni][half * 2 + 0], 0.f);
                m.y = fmaxf(xv.y + acc[ni][half * 2 + 1], 0.f);
                red_add_v2(agg + drow + col, m);
            }
        }
    }
}

// ---------------- fused two-stage node GEMM ------------------------------------
// out = act2( act1(A @ W1 + b1) @ W2 + b2 ). Persistent, 256 thr (8 warps),
// M-tile 128. W1,W2 resident in smem; T tile overwrites the A tile buffer.
// Warp (mw,cw): rows [64*mw,+64) x cols [32*cw,+32) (stage2: NW2*cw).
// ACT: 1 = relu, 2 = tanh, 0 = none.
template <int COUT2, int ACT1, int ACT2>
__global__ void __launch_bounds__(256, 1)
fgemm(const float* __restrict__ A,
      const __nv_bfloat16* __restrict__ W1h, const __nv_bfloat16* __restrict__ W1l,
      const __nv_bfloat16* __restrict__ W2h, const __nv_bfloat16* __restrict__ W2l,
      const float* __restrict__ b1, const float* __restrict__ b2,
      float* __restrict__ out, float* __restrict__ out2, int nrows, int ntiles) {
    constexpr int NW2 = COUT2 / 4;
    constexpr int NF2 = NW2 / 8;
    constexpr uint32_t AB  = 128 * 136 * 2;        // 34816 (per hi/lo buffer)
    constexpr uint32_t W1B = 128 * 136 * 2;
    constexpr uint32_t W2B = (uint32_t)COUT2 * 136 * 2;

    extern __shared__ char sm[];
    const uint32_t s0   = smem_u32(sm);
    const uint32_t sAh  = s0,            sAl  = s0 + AB;
    const uint32_t sW1h = s0 + 2 * AB,   sW1l = sW1h + W1B;
    const uint32_t sW2h = sW1l + W1B,    sW2l = sW2h + W2B;

    const int tid  = threadIdx.x;
    const int wid  = tid >> 5;
    const int lane = tid & 31;
    const int mw   = wid >> 2, cw = wid & 3;

    // resident weights, loaded once
    for (int i = tid; i < (int)(W1B / 16); i += 256) {
        cp_async16(sW1h + i * 16, (const char*)W1h + i * 16);
        cp_async16(sW1l + i * 16, (const char*)W1l + i * 16);
    }
    for (int i = tid; i < (int)(W2B / 16); i += 256) {
        cp_async16(sW2h + i * 16, (const char*)W2h + i * 16);
        cp_async16(sW2l + i * 16, (const char*)W2l + i * 16);
    }
    cp_commit();

    const int g = lane >> 2, tq = lane & 3;
    const uint32_t aoff = (uint32_t)(mw * 64 + (lane & 15)) * 272
                        + ((lane >> 4) ? 16 : 0);
    const int brow = (lane & 7) + ((lane >> 4) << 3);
    const uint32_t b1off = (uint32_t)(cw * 32 + brow) * 272 + ((lane & 8) ? 16 : 0);
    const uint32_t b2off = (uint32_t)(cw * NW2 + brow) * 272 + ((lane & 8) ? 16 : 0);

    bool first = true;
    for (int mt = blockIdx.x; mt < ntiles; mt += gridDim.x) {
        const int mbase = mt * 128;

        // ---- load/convert A tile (128 x 128 fp32 -> bf16 hi/lo, pitch 136) ----
        {
            const int row = tid >> 1, half = tid & 1;
            int grow = min(mbase + row, nrows - 1);
            const float* ap = A + (size_t)grow * 128 + half * 64;
            const uint32_t d = row * 272 + half * 128;
#pragma unroll
            for (int i = 0; i < 8; i++) {
                float4 v0 = *(const float4*)(ap + i * 8);
                float4 v1 = *(const float4*)(ap + i * 8 + 4);
                uint32_t l0, l1, l2, l3;
                uint32_t h0 = split_hi2(v0.x, v0.y, l0);
                uint32_t h1 = split_hi2(v0.z, v0.w, l1);
                uint32_t h2 = split_hi2(v1.x, v1.y, l2);
                uint32_t h3 = split_hi2(v1.z, v1.w, l3);
                asm volatile("st.shared.v4.b32 [%0], {%1, %2, %3, %4};"
                             :: "r"(sAh + d + i * 16), "r"(h0), "r"(h1), "r"(h2), "r"(h3));
                asm volatile("st.shared.v4.b32 [%0], {%1, %2, %3, %4};"
                             :: "r"(sAl + d + i * 16), "r"(l0), "r"(l1), "r"(l2), "r"(l3));
            }
        }
        if (first) { cp_wait0(); first = false; }
        __syncthreads();

        // ---- stage 1: T = act1(A @ W1 + b1) ----
        float acc[4][4][4];
#pragma unroll
        for (int ni = 0; ni < 4; ni++) {
            float2 b = __ldg((const float2*)(b1 + cw * 32 + ni * 8 + tq * 2));
#pragma unroll
            for (int mi = 0; mi < 4; mi++) {
                acc[mi][ni][0] = b.x; acc[mi][ni][1] = b.y;
                acc[mi][ni][2] = b.x; acc[mi][ni][3] = b.y;
            }
        }
#pragma unroll
        for (int ks = 0; ks < 8; ks++) {
            uint32_t ah[4][4], al[4][4], bh[4][2], bl[4][2];
#pragma unroll
            for (int mi = 0; mi < 4; mi++) {
                ldx4(ah[mi], sAh + aoff + mi * 4352 + ks * 32);
                ldx4(al[mi], sAl + aoff + mi * 4352 + ks * 32);
            }
#pragma unroll
            for (int np = 0; np < 2; np++) {
                uint32_t r[4];
                ldx4(r, sW1h + b1off + np * 4352 + ks * 32);
                bh[np * 2][0] = r[0]; bh[np * 2][1] = r[1];
                bh[np * 2 + 1][0] = r[2]; bh[np * 2 + 1][1] = r[3];
                ldx4(r, sW1l + b1off + np * 4352 + ks * 32);
                bl[np * 2][0] = r[0]; bl[np * 2][1] = r[1];
                bl[np * 2 + 1][0] = r[2]; bl[np * 2 + 1][1] = r[3];
            }
#pragma unroll
            for (int mi = 0; mi < 4; mi++)
#pragma unroll
                for (int ni = 0; ni < 4; ni++) {
                    mma_bf16(acc[mi][ni], ah[mi], bh[ni]);
                    mma_bf16(acc[mi][ni], ah[mi], bl[ni]);
                    mma_bf16(acc[mi][ni], al[mi], bh[ni]);
                }
        }
        __syncthreads();      // all A reads done before T overwrites the buffer

        // ---- write T (act1, bf16 split) into the A buffer ----
#pragma unroll
        for (int mi = 0; mi < 4; mi++) {
            const int r0 = mw * 64 + mi * 16 + g;
#pragma unroll
            for (int ni = 0; ni < 4; ni++) {
                const int col = cw * 32 + ni * 8 + tq * 2;
                float v0 = acc[mi][ni][0], v1 = acc[mi][ni][1];
                float v2 = acc[mi][ni][2], v3 = acc[mi][ni][3];
                if (ACT1 == 1) {
                    v0 = fmaxf(v0, 0.f); v1 = fmaxf(v1, 0.f);
                    v2 = fmaxf(v2, 0.f); v3 = fmaxf(v3, 0.f);
                } else {
                    v0 = tanhf(v0); v1 = tanhf(v1);
                    v2 = tanhf(v2); v3 = tanhf(v3);
                }
                uint32_t lo0, lo1;
                uint32_t hi0 = split_hi2(v0, v1, lo0);
                uint32_t hi1 = split_hi2(v2, v3, lo1);
                const uint32_t d0 = (uint32_t)r0 * 272 + col * 2;
                asm volatile("st.shared.b32 [%0], %1;" :: "r"(sAh + d0), "r"(hi0));
                asm volatile("st.shared.b32 [%0], %1;" :: "r"(sAl + d0), "r"(lo0));
                asm volatile("st.shared.b32 [%0], %1;" :: "r"(sAh + d0 + 8 * 272), "r"(hi1));
                asm volatile("st.shared.b32 [%0], %1;" :: "r"(sAl + d0 + 8 * 272), "r"(lo1));
            }
        }
        __syncthreads();

        // ---- stage 2: out = act2(T @ W2 + b2) ----
        float acc2[4][NF2][4];
#pragma unroll
        for (int ni = 0; ni < NF2; ni++) {
            float2 b = __ldg((const float2*)(b2 + cw * NW2 + ni * 8 + tq * 2));
#pragma unroll
            for (int mi = 0; mi < 4; mi++) {
                acc2[mi][ni][0] = b.x; acc2[mi][ni][1] = b.y;
                acc2[mi][ni][2] = b.x; acc2[mi][ni][3] = b.y;
            }
        }
#pragma unroll
        for (int ks = 0; ks < 8; ks++) {
            uint32_t ah[4][4], al[4][4], bh[NF2][2], bl[NF2][2];
#pragma unroll
            for (int mi = 0; mi < 4; mi++) {
                ldx4(ah[mi], sAh + aoff + mi * 4352 + ks * 32);
                ldx4(al[mi], sAl + aoff + mi * 4352 + ks * 32);
            }
#pragma unroll
            for (int np = 0; np < NF2 / 2; np++) {
                uint32_t r[4];
                ldx4(r, sW2h + b2off + np * 4352 + ks * 32);
                bh[np * 2][0] = r[0]; bh[np * 2][1] = r[1];
                bh[np * 2 + 1][0] = r[2]; bh[np * 2 + 1][1] = r[3];
                ldx4(r, sW2l + b2off + np * 4352 + ks * 32);
                bl[np * 2][0] = r[0]; bl[np * 2][1] = r[1];
                bl[np * 2 + 1][0] = r[2]; bl[np * 2 + 1][1] = r[3];
            }
#pragma unroll
            for (int mi = 0; mi < 4; mi++)
#pragma unroll
                for (int ni = 0; ni < NF2; ni++) {
                    mma_bf16(acc2[mi][ni], ah[mi], bh[ni]);
                    mma_bf16(acc2[mi][ni], ah[mi], bl[ni]);
                    mma_bf16(acc2[mi][ni], al[mi], bh[ni]);
                }
        }
        __syncthreads();      // T reads done before next tile's A load

        // ---- epilogue ----
#pragma unroll
        for (int mi = 0; mi < 4; mi++) {
            const int r0 = mbase + mw * 64 + mi * 16 + g;
#pragma unroll
            for (int ni = 0; ni < NF2; ni++) {
                const int col = cw * NW2 + ni * 8 + tq * 2;
                float v0 = acc2[mi][ni][0], v1 = acc2[mi][ni][1];
                float v2 = acc2[mi][ni][2], v3 = acc2[mi][ni][3];
                if (ACT2 == 2) {
                    v0 = tanhf(v0); v1 = tanhf(v1);
                    v2 = tanhf(v2); v3 = tanhf(v3);
                }
                if (r0 < nrows) {
                    *(float2*)(out + (size_t)r0 * COUT2 + col) = make_float2(v0, v1);
                    if (out2)
                        *(float2*)(out2 + (size_t)r0 * COUT2 + col) = make_float2(v0, v1);
                }
                if (r0 + 8 < nrows) {
                    *(float2*)(out + (size_t)(r0 + 8) * COUT2 + col) = make_float2(v2, v3);
                    if (out2)
                        *(float2*)(out2 + (size_t)(r0 + 8) * COUT2 + col) = make_float2(v2, v3);
                }
            }
        }
    }
}

// ---------------- launch ------------------------------------------------------
extern "C" void kernel_launch(void* const* d_in, const int* in_sizes, int n_in,
                              void* d_out, int out_size) {
    const float* x    = (const float*)d_in[0];
    const int*   ei   = (const int*)d_in[1];
    const float* ef   = (const float*)d_in[2];
    const float* be1  = (const float*)d_in[4];
    const float* W1a  = (const float*)d_in[5];
    const float* b1a  = (const float*)d_in[6];
    const float* W1b  = (const float*)d_in[7];
    const float* b1b  = (const float*)d_in[8];
    const float* We1  = (const float*)d_in[3];
    const float* We2  = (const float*)d_in[9];
    const float* be2  = (const float*)d_in[10];
    const float* W2a  = (const float*)d_in[11];
    const float* b2a  = (const float*)d_in[12];
    const float* W2b  = (const float*)d_in[13];
    const float* b2b  = (const float*)d_in[14];
    const float* Wfc1 = (const float*)d_in[15];
    const float* bfc1 = (const float*)d_in[16];
    const float* Wfc2 = (const float*)d_in[17];
    const float* bfc2 = (const float*)d_in[18];
    float* out = (float*)d_out;

    float *agg, *h;
    __nv_bfloat16 *wb, *web;
    cudaGetSymbolAddress((void**)&agg, g_agg);
    cudaGetSymbolAddress((void**)&h,   g_h);
    cudaGetSymbolAddress((void**)&wb,  g_wb);
    cudaGetSymbolAddress((void**)&web, g_web);
    auto WB = [&](int m, int s) { return wb + ((size_t)m * 2 + s) * 128 * 136; };
    auto WE = [&](int m, int s) { return web + ((size_t)m * 2 + s) * 128 * 40; };

    const int* srcp = ei;
    const int* dstp = ei + Ee;

    const int n4 = Nn * 128 / 4;
    const int cpG = (n4 + 255) / 256;
    const int egG = (Ee + 127) / 128;            // 4688
    const int ntiles = (Nn + 127) / 128;         // 782

    constexpr int SMF128 = 6 * 128 * 136 * 2;            // 208896
    constexpr int SMF64  = 4 * 128 * 136 * 2 + 2 * 64 * 136 * 2;  // 174080
    cudaFuncSetAttribute(fgemm<128, 1, 2>, cudaFuncAttributeMaxDynamicSharedMemorySize, SMF128);
    cudaFuncSetAttribute(fgemm<64, 2, 0>,  cudaFuncAttributeMaxDynamicSharedMemorySize, SMF64);

    // 1: all weight prep in one launch
    prep_all<<<384, 256>>>(W1a, W1b, W2a, W2b, Wfc1, Wfc2, We1, We2, wb, web);

    // Layer 1
    copy_kernel<<<cpG, 256>>>((float4*)agg, (const float4*)x, n4);
    edge_kernel<<<egG, 256>>>(x, srcp, dstp, ef, WE(0, 0), WE(0, 1), be1, agg);
    fgemm<128, 1, 2><<<148, 256, SMF128>>>(agg, WB(0, 0), WB(0, 1), WB(1, 0), WB(1, 1),
                                           b1a, b1b, h, agg, Nn, ntiles);

    // Layer 2
    edge_kernel<<<egG, 256>>>(h, srcp, dstp, ef, WE(1, 0), WE(1, 1), be2, agg);
    fgemm<128, 1, 2><<<148, 256, SMF128>>>(agg, WB(2, 0), WB(2, 1), WB(3, 0), WB(3, 1),
                                           b2a, b2b, h, nullptr, Nn, ntiles);

    // Head: tanh(h@Wfc1+bfc1)@Wfc2+bfc2
    fgemm<64, 2, 0><<<148, 256, SMF64>>>(h, WB(4, 0), WB(4, 1), WB(5, 0), WB(5, 1),
                                         bfc1, bfc2, out, nullptr, Nn, ntiles);
}